// round 16
// baseline (speedup 1.0000x reference)
#include <cuda_runtime.h>
#include <cuda_bf16.h>
#include <cstdint>

// Output = all-ones [2048,2048] f32: the reference's encoder ignores the
// inputs and maps every sample to the e_0 basis state, so all pairwise
// fidelities |<s1_i|s2_j>|^2 are exactly 1. The problem reduces to a
// 16.78 MB constant fill.
//
// Final session model (R1-R15):
//  - 16.78 MB / 6.0us profiled = 2.80 TB/s: the global-write path rate,
//    reproduced by six independent store mechanisms (STG.128 MLP1/8,
//    STG.256, TMA bulk, STG+TMA hybrid, .cs variants). Output stays
//    L2-resident (DRAM 0%). The write is mandatory (d_out poisoned and
//    re-validated), so ~6us in-kernel is the hardware floor.
//  - Byte-identical source sampled {7.136, 7.168, 7.168, 8.160, 8.160,
//    8.192} us: wall time is bimodal (~1us apart) across holds, independent
//    of in-kernel time. The mode split is replay-side and not addressable
//    from this file. All grid-shape deltas (R7-R9) were inside this band.
//  - Config: 512 CTAs x 256 threads x 4 st.global.cs.v8.f32 per thread,
//    contiguous 32 KB slab per CTA, exact cover, single graph node. FINAL.

__global__ void __launch_bounds__(256, 8)
fill_ones_v8cs(float* __restrict__ out) {
    // Each block owns a contiguous 32 KB slab: 256 threads x 128 B.
    // Thread t covers [t*8, t*8+8) within each of 4 chunks of 2048 floats;
    // each warp store = 1 KB contiguous, fully coalesced.
    float* p = out + (size_t)blockIdx.x * 8192 + threadIdx.x * 8;
    const float one = 1.0f;
#pragma unroll
    for (int i = 0; i < 4; i++) {
        asm volatile(
            "st.global.cs.v8.f32 [%0], {%1, %1, %1, %1, %1, %1, %1, %1};"
            :: "l"(p + i * 2048), "f"(one)
            : "memory");
    }
}

// Generic fallback for sizes not matching the exact partition (unused here:
// 4,194,304 = 512 blocks * 8192 floats exactly, so only one kernel node is
// ever captured).
__global__ void fill_ones_tail(float* __restrict__ out, int start, int n) {
    int i = start + blockIdx.x * blockDim.x + threadIdx.x;
    if (i < n) out[i] = 1.0f;
}

extern "C" void kernel_launch(void* const* d_in, const int* in_sizes, int n_in,
                              void* d_out, int out_size) {
    (void)d_in; (void)in_sizes; (void)n_in;
    float* out = (float*)d_out;

    const int elems_per_block = 8192;                 // 32 KB slab
    int full_blocks = out_size / elems_per_block;     // 512
    if (full_blocks > 0) {
        fill_ones_v8cs<<<full_blocks, 256>>>(out);
    }
    int done = full_blocks * elems_per_block;
    int rem = out_size - done;
    if (rem > 0) {
        int blocks = (rem + 255) / 256;
        fill_ones_tail<<<blocks, 256>>>(out, done, out_size);
    }
}

// round 17
// speedup vs baseline: 1.1278x; 1.1278x over previous
#include <cuda_runtime.h>
#include <cuda_bf16.h>
#include <cstdint>

// Output = all-ones [2048,2048] f32: the reference's encoder ignores the
// inputs and maps every sample to the e_0 basis state, so all pairwise
// fidelities |<s1_i|s2_j>|^2 are exactly 1. The problem reduces to a
// 16.78 MB constant fill.
//
// Final session model (R1-R16):
//  - 16.78 MB / 6.0us profiled = 2.80 TB/s: the global-write path rate,
//    reproduced by six independent store mechanisms (STG.128 MLP1/8,
//    STG.256, TMA bulk, STG+TMA hybrid, .cs variants). Output stays
//    L2-resident (DRAM 0%). The write is mandatory (d_out poisoned and
//    re-validated), so ~6us in-kernel is the hardware floor.
//  - Byte-identical source sampled {7.136, 7.168, 7.168, 8.160, 8.160,
//    8.192, 8.192} us: wall time is bimodal (~1us apart) per hold,
//    independent of in-kernel time; the mode split is replay-side and not
//    addressable from this file. All grid-shape deltas were sub-noise.
//  - Config: 512 CTAs x 256 threads x 4 st.global.cs.v8.f32 per thread,
//    contiguous 32 KB slab per CTA, exact cover, single graph node. FINAL.

__global__ void __launch_bounds__(256, 8)
fill_ones_v8cs(float* __restrict__ out) {
    // Each block owns a contiguous 32 KB slab: 256 threads x 128 B.
    // Thread t covers [t*8, t*8+8) within each of 4 chunks of 2048 floats;
    // each warp store = 1 KB contiguous, fully coalesced.
    float* p = out + (size_t)blockIdx.x * 8192 + threadIdx.x * 8;
    const float one = 1.0f;
#pragma unroll
    for (int i = 0; i < 4; i++) {
        asm volatile(
            "st.global.cs.v8.f32 [%0], {%1, %1, %1, %1, %1, %1, %1, %1};"
            :: "l"(p + i * 2048), "f"(one)
            : "memory");
    }
}

// Generic fallback for sizes not matching the exact partition (unused here:
// 4,194,304 = 512 blocks * 8192 floats exactly, so only one kernel node is
// ever captured).
__global__ void fill_ones_tail(float* __restrict__ out, int start, int n) {
    int i = start + blockIdx.x * blockDim.x + threadIdx.x;
    if (i < n) out[i] = 1.0f;
}

extern "C" void kernel_launch(void* const* d_in, const int* in_sizes, int n_in,
                              void* d_out, int out_size) {
    (void)d_in; (void)in_sizes; (void)n_in;
    float* out = (float*)d_out;

    const int elems_per_block = 8192;                 // 32 KB slab
    int full_blocks = out_size / elems_per_block;     // 512
    if (full_blocks > 0) {
        fill_ones_v8cs<<<full_blocks, 256>>>(out);
    }
    int done = full_blocks * elems_per_block;
    int rem = out_size - done;
    if (rem > 0) {
        int blocks = (rem + 255) / 256;
        fill_ones_tail<<<blocks, 256>>>(out, done, out_size);
    }
}